// round 8
// baseline (speedup 1.0000x reference)
#include <cuda_runtime.h>
#include <cuda_bf16.h>

// Problem constants
#define NMAX   50000
#define EMAX   800000
#define TOTMAX (EMAX + NMAX)
#define GRAPHS 256
#define HC     256      // H*C
#define KIN    300      // n_in
#define FOUT   768      // nout

// ---------------- scratch (device globals; no allocation) ----------------
__device__ float  g_h[NMAX * HC];          // node features after linear [N,256]
__device__ float  g_asrc[NMAX * 4];        // per-node src attention logits [N,4]
__device__ float  g_adst[NMAX * 4];        // per-node dst attention logits [N,4]
__device__ int    g_count[NMAX];           // in-degree (incl self-loop)
__device__ int    g_scanex[NMAX];          // per-chunk exclusive scan
__device__ int    g_bsum[64];              // chunk totals -> chunk offsets
__device__ int    g_rowoff[NMAX];          // CSR row offsets
__device__ int    g_cursor[NMAX];          // fill cursors
__device__ int    g_csrc[TOTMAX];          // CSR-ordered src ids
__device__ float4 g_cee[TOTMAX];           // CSR-ordered exp weights (per head)
__device__ float  g_pool[GRAPHS * HC];     // per-graph sums [G,256]
__device__ float  g_pooled[GRAPHS * HC];   // normalized pooled features
__device__ float  g_cnt[GRAPHS];           // per-graph node counts

// ---------------- 0: init scratch ----------------
__global__ void init_kernel(int M) {
    int i = blockIdx.x * blockDim.x + threadIdx.x;
    if (i < M)            g_count[i] = 1;   // self-loop pre-counted
    if (i < GRAPHS * HC)  g_pool[i]  = 0.0f;
    if (i < GRAPHS)       g_cnt[i]   = 0.0f;
}

// ---------------- 1: h = x @ lin_w (+ fused attention dots), fp32 SIMT ----------------
// 128x128 tile, BK=8, 256 threads, 8x8 per thread, double-buffered smem.
#define BM 128
#define BN 128
#define BK 8
#define NCH ((KIN + BK - 1) / BK)
__global__ __launch_bounds__(256, 2)
void gemm_h_kernel(const float* __restrict__ X,
                   const float* __restrict__ W,
                   const float* __restrict__ att_s,
                   const float* __restrict__ att_d,
                   int M) {
    __shared__ float As[2][BK][BM];
    __shared__ float Bs[2][BK][BN];
    __shared__ float s_as[BN], s_ad[BN];

    const int bx   = blockIdx.x;              // 0..1 -> N offset bx*128 (heads bx*2, bx*2+1)
    const int row0 = blockIdx.y * BM;
    const int tid  = threadIdx.x;
    const int tx   = tid & 15;
    const int ty   = tid >> 4;

    if (tid < BN) { s_as[tid] = att_s[bx * BN + tid]; s_ad[tid] = att_d[bx * BN + tid]; }

    float acc[2][2][4][4];
#pragma unroll
    for (int a = 0; a < 2; a++)
#pragma unroll
        for (int b = 0; b < 2; b++)
#pragma unroll
            for (int i = 0; i < 4; i++)
#pragma unroll
                for (int j = 0; j < 4; j++) acc[a][b][i][j] = 0.0f;

    const int arow  = tid >> 1;             // 0..127
    const int akb   = (tid & 1) * 4;        // 0 or 4
    const int bkk   = tid >> 5;             // 0..7
    const int bcol  = (tid & 31) * 4;       // 0..124
    const int garow = row0 + arow;

    float4 rA, rB;
    // prologue: load chunk 0
    {
        int gk = akb;
        rA = (garow < M && gk < KIN) ? *(const float4*)&X[garow * KIN + gk]
                                     : make_float4(0.f, 0.f, 0.f, 0.f);
        rB = (bkk < KIN) ? *(const float4*)&W[bkk * HC + bx * BN + bcol]
                         : make_float4(0.f, 0.f, 0.f, 0.f);
        As[0][akb + 0][arow] = rA.x;
        As[0][akb + 1][arow] = rA.y;
        As[0][akb + 2][arow] = rA.z;
        As[0][akb + 3][arow] = rA.w;
        *(float4*)&Bs[0][bkk][bcol] = rB;
    }
    __syncthreads();

    for (int c = 0; c < NCH; c++) {
        const int buf = c & 1;
        // prefetch next chunk into registers (overlaps with compute below)
        if (c + 1 < NCH) {
            int gk = (c + 1) * BK;
            int ga = gk + akb, gb = gk + bkk;
            rA = (garow < M && ga < KIN) ? *(const float4*)&X[garow * KIN + ga]
                                         : make_float4(0.f, 0.f, 0.f, 0.f);
            rB = (gb < KIN) ? *(const float4*)&W[gb * HC + bx * BN + bcol]
                            : make_float4(0.f, 0.f, 0.f, 0.f);
        }
#pragma unroll
        for (int kk = 0; kk < BK; kk++) {
            float4 a0 = *(const float4*)&As[buf][kk][ty * 4];
            float4 a1 = *(const float4*)&As[buf][kk][64 + ty * 4];
            float4 b0 = *(const float4*)&Bs[buf][kk][tx * 4];
            float4 b1 = *(const float4*)&Bs[buf][kk][64 + tx * 4];
            float av[2][4] = {{a0.x, a0.y, a0.z, a0.w}, {a1.x, a1.y, a1.z, a1.w}};
            float bv[2][4] = {{b0.x, b0.y, b0.z, b0.w}, {b1.x, b1.y, b1.z, b1.w}};
#pragma unroll
            for (int a = 0; a < 2; a++)
#pragma unroll
                for (int b = 0; b < 2; b++)
#pragma unroll
                    for (int i = 0; i < 4; i++)
#pragma unroll
                        for (int j = 0; j < 4; j++)
                            acc[a][b][i][j] += av[a][i] * bv[b][j];
        }
        // store prefetched chunk into the other buffer (read at c-1 finished pre-sync)
        if (c + 1 < NCH) {
            const int nb = buf ^ 1;
            As[nb][akb + 0][arow] = rA.x;
            As[nb][akb + 1][arow] = rA.y;
            As[nb][akb + 2][arow] = rA.z;
            As[nb][akb + 3][arow] = rA.w;
            *(float4*)&Bs[nb][bkk][bcol] = rB;
        }
        __syncthreads();
    }

    // epilogue: store h + fused attention dots
#pragma unroll
    for (int a = 0; a < 2; a++) {
#pragma unroll
        for (int i = 0; i < 4; i++) {
            int gr = row0 + a * 64 + ty * 4 + i;
            bool ok = gr < M;
#pragma unroll
            for (int b = 0; b < 2; b++) {
                if (ok) {
                    *(float4*)&g_h[gr * HC + bx * BN + b * 64 + tx * 4] =
                        make_float4(acc[a][b][i][0], acc[a][b][i][1],
                                    acc[a][b][i][2], acc[a][b][i][3]);
                }
                float s = 0.f, d = 0.f;
#pragma unroll
                for (int j = 0; j < 4; j++) {
                    s += acc[a][b][i][j] * s_as[b * 64 + tx * 4 + j];
                    d += acc[a][b][i][j] * s_ad[b * 64 + tx * 4 + j];
                }
#pragma unroll
                for (int off = 8; off > 0; off >>= 1) {
                    s += __shfl_down_sync(0xffffffffu, s, off, 16);
                    d += __shfl_down_sync(0xffffffffu, d, off, 16);
                }
                if (ok && tx == 0) {
                    g_asrc[gr * 4 + bx * 2 + b] = s;
                    g_adst[gr * 4 + bx * 2 + b] = d;
                }
            }
        }
    }
}

// ---------------- 2: degree count (dst only; self-loops pre-counted) ----------------
__global__ void edge_count_kernel(const int* __restrict__ ei, int E) {
    int i = blockIdx.x * blockDim.x + threadIdx.x;
    if (i >= E) return;
    atomicAdd(&g_count[ei[E + i]], 1);
}

// ---------------- 3: 2-level exclusive scan of g_count ----------------
__global__ void scan1_kernel(int M) {                     // block=1024
    __shared__ int sh[2][1024];
    int i = blockIdx.x * 1024 + threadIdx.x;
    int v = (i < M) ? g_count[i] : 0;
    int buf = 0;
    sh[0][threadIdx.x] = v;
    __syncthreads();
#pragma unroll
    for (int off = 1; off < 1024; off <<= 1) {
        int nv = sh[buf][threadIdx.x];
        if (threadIdx.x >= off) nv += sh[buf][threadIdx.x - off];
        sh[1 - buf][threadIdx.x] = nv;
        buf = 1 - buf;
        __syncthreads();
    }
    int incl = sh[buf][threadIdx.x];
    if (i < M) g_scanex[i] = incl - v;
    if (threadIdx.x == 1023) g_bsum[blockIdx.x] = incl;
}

__global__ void scan2_kernel(int nb) {                    // 1 thread
    int run = 0;
    for (int b = 0; b < nb; b++) { int t = g_bsum[b]; g_bsum[b] = run; run += t; }
}

__global__ void scan3_kernel(int M) {
    int i = blockIdx.x * blockDim.x + threadIdx.x;
    if (i >= M) return;
    int off = g_scanex[i] + g_bsum[i >> 10];
    g_rowoff[i] = off;
    g_cursor[i] = off;
}

// ---------------- 4: CSR fill (recomputes leaky+exp; no g_e round-trip) ----------------
__global__ void edge_fill_kernel(const int* __restrict__ ei, int E, int M) {
    int i = blockIdx.x * blockDim.x + threadIdx.x;
    int total = E + M;
    if (i >= total) return;
    int s, d;
    if (i < E) { s = ei[i]; d = ei[E + i]; }
    else       { s = d = i - E; }
    float4 as = ((const float4*)g_asrc)[s];
    float4 ad = ((const float4*)g_adst)[d];
    float e0 = as.x + ad.x, e1 = as.y + ad.y, e2 = as.z + ad.z, e3 = as.w + ad.w;
    e0 = e0 > 0.f ? e0 : 0.2f * e0;
    e1 = e1 > 0.f ? e1 : 0.2f * e1;
    e2 = e2 > 0.f ? e2 : 0.2f * e2;
    e3 = e3 > 0.f ? e3 : 0.2f * e3;
    float4 ee = make_float4(__expf(e0), __expf(e1), __expf(e2), __expf(e3));
    int pos = atomicAdd(&g_cursor[d], 1);
    g_csrc[pos] = s;
    g_cee[pos]  = ee;
}

// ---------------- 5: gather-aggregate (warp per node) + denom + bias + leaky + pool ----------------
__global__ void aggregate_kernel(const int* __restrict__ batch,
                                 const float* __restrict__ bias, int M) {
    int w = blockIdx.x * (blockDim.x >> 5) + (threadIdx.x >> 5);
    if (w >= M) return;
    int lane = threadIdx.x & 31;
    int start = g_rowoff[w];
    int end   = start + g_count[w];
    int hsel  = lane >> 3;                      // head for this thread's 8 channels

    float acc[8];
#pragma unroll
    for (int k = 0; k < 8; k++) acc[k] = 0.0f;
    float wsum = 0.0f;

    int src = 0; float4 ee = make_float4(0, 0, 0, 0);
    if (start < end) { src = g_csrc[start]; ee = g_cee[start]; }
    for (int j = start; j < end; j++) {
        int nsrc = 0; float4 nee = ee;
        if (j + 1 < end) { nsrc = g_csrc[j + 1]; nee = g_cee[j + 1]; }
        const float4* hp = (const float4*)&g_h[(long long)src * HC + lane * 8];
        float4 h0 = hp[0], h1 = hp[1];
        float wgt = (hsel == 0) ? ee.x : (hsel == 1) ? ee.y : (hsel == 2) ? ee.z : ee.w;
        wsum += wgt;
        acc[0] += h0.x * wgt; acc[1] += h0.y * wgt;
        acc[2] += h0.z * wgt; acc[3] += h0.w * wgt;
        acc[4] += h1.x * wgt; acc[5] += h1.y * wgt;
        acc[6] += h1.z * wgt; acc[7] += h1.w * wgt;
        src = nsrc; ee = nee;
    }

    float inv = 1.0f / wsum;
    int b = batch[w];
    float* pp = &g_pool[b * HC + lane * 8];
#pragma unroll
    for (int k = 0; k < 8; k++) {
        float v = acc[k] * inv + bias[lane * 8 + k];
        v = v > 0.f ? v : 0.01f * v;
        atomicAdd(&pp[k], v);
    }
    if (lane == 0) atomicAdd(&g_cnt[b], 1.0f);
}

// ---------------- 6a: normalize pooled sums ----------------
__global__ void pool_norm_kernel() {
    int i = blockIdx.x * blockDim.x + threadIdx.x;
    if (i >= GRAPHS * HC) return;
    int g = i >> 8;
    g_pooled[i] = g_pool[i] / fmaxf(g_cnt[g], 1.0f);
}

// ---------------- 6b: out = pooled @ fc1_w + fc1_b, tiled ----------------
#define FBM 32
#define FBN 64
#define SPP 260
__global__ __launch_bounds__(256)
void fc_kernel(const float* __restrict__ fc1_w,
               const float* __restrict__ fc1_b,
               float* __restrict__ out) {
    __shared__ float sp[FBM * SPP];
    __shared__ float sw[32][FBN];
    const int g0  = blockIdx.y * FBM;
    const int n0  = blockIdx.x * FBN;
    const int tid = threadIdx.x;

#pragma unroll
    for (int it = 0; it < 8; it++) {
        int i = tid + it * 256;
        int r = i >> 6;
        int c = (i & 63) * 4;
        *(float4*)&sp[r * SPP + c] = *(const float4*)&g_pooled[(g0 + r) * HC + c];
    }

    const int row = tid >> 3;
    const int cg  = (tid & 7) * 8;
    float acc[8];
#pragma unroll
    for (int j = 0; j < 8; j++) acc[j] = 0.0f;

    for (int k0 = 0; k0 < HC; k0 += 32) {
        __syncthreads();
#pragma unroll
        for (int it = 0; it < 2; it++) {
            int i = tid + it * 256;
            int r = i >> 4;
            int c = (i & 15) * 4;
            *(float4*)&sw[r][c] = *(const float4*)&fc1_w[(k0 + r) * FOUT + n0 + c];
        }
        __syncthreads();
#pragma unroll
        for (int kk = 0; kk < 32; kk++) {
            float p = sp[row * SPP + k0 + kk];
            float4 w0 = *(const float4*)&sw[kk][cg];
            float4 w1 = *(const float4*)&sw[kk][cg + 4];
            acc[0] += p * w0.x; acc[1] += p * w0.y;
            acc[2] += p * w0.z; acc[3] += p * w0.w;
            acc[4] += p * w1.x; acc[5] += p * w1.y;
            acc[6] += p * w1.z; acc[7] += p * w1.w;
        }
    }
#pragma unroll
    for (int j = 0; j < 8; j++) acc[j] += fc1_b[n0 + cg + j];
    *(float4*)&out[(g0 + row) * FOUT + n0 + cg]     = make_float4(acc[0], acc[1], acc[2], acc[3]);
    *(float4*)&out[(g0 + row) * FOUT + n0 + cg + 4] = make_float4(acc[4], acc[5], acc[6], acc[7]);
}

// ---------------- launch ----------------
extern "C" void kernel_launch(void* const* d_in, const int* in_sizes, int n_in,
                              void* d_out, int out_size) {
    const float* x     = (const float*)d_in[0];
    const int*   ei    = (const int*)d_in[1];
    const int*   batch = (const int*)d_in[2];
    const float* lin_w = (const float*)d_in[3];
    const float* att_s = (const float*)d_in[4];
    const float* att_d = (const float*)d_in[5];
    const float* bias  = (const float*)d_in[6];
    const float* fc1_w = (const float*)d_in[7];
    const float* fc1_b = (const float*)d_in[8];
    float* out = (float*)d_out;

    int M = in_sizes[2];       // nodes
    int E = in_sizes[1] / 2;   // edges
    int total = E + M;

    int initN = M > GRAPHS * HC ? M : GRAPHS * HC;
    init_kernel<<<(initN + 255) / 256, 256>>>(M);              // 0

    edge_count_kernel<<<(E + 255) / 256, 256>>>(ei, E);        // 1

    int nb = (M + 1023) / 1024;
    scan1_kernel<<<nb, 1024>>>(M);                             // 2

    dim3 ggrid(2, (M + BM - 1) / BM);
    gemm_h_kernel<<<ggrid, 256>>>(x, lin_w, att_s, att_d, M);  // 3 <- ncu capture slot

    scan2_kernel<<<1, 1>>>(nb);                                // 4
    scan3_kernel<<<(M + 255) / 256, 256>>>(M);                 // 5

    edge_fill_kernel<<<(total + 255) / 256, 256>>>(ei, E, M);  // 6

    aggregate_kernel<<<(M * 32 + 255) / 256, 256>>>(batch, bias, M);  // 7

    pool_norm_kernel<<<(GRAPHS * HC + 255) / 256, 256>>>();    // 8

    dim3 fgrid(FOUT / FBN, GRAPHS / FBM);
    fc_kernel<<<fgrid, 256>>>(fc1_w, fc1_b, out);              // 9
}

// round 9
// speedup vs baseline: 1.0062x; 1.0062x over previous
#include <cuda_runtime.h>
#include <cuda_bf16.h>

// Problem constants
#define NMAX   50000
#define EMAX   800000
#define TOTMAX (EMAX + NMAX)
#define GRAPHS 256
#define HC     256      // H*C
#define KIN    300      // n_in
#define FOUT   768      // nout

// ---------------- scratch (device globals; no allocation) ----------------
__device__ float  g_h[NMAX * HC];          // node features after linear [N,256]
__device__ float  g_asrc[NMAX * 4];        // per-node src attention logits [N,4]
__device__ float  g_adst[NMAX * 4];        // per-node dst attention logits [N,4]
__device__ int    g_count[NMAX];           // in-degree (incl self-loop)
__device__ int    g_scanex[NMAX];          // per-chunk exclusive scan
__device__ int    g_bsum[64];              // chunk totals -> chunk offsets
__device__ int    g_rowoff[NMAX];          // CSR row offsets
__device__ int    g_cursor[NMAX];          // fill cursors
__device__ int    g_csrc[TOTMAX];          // CSR-ordered src ids
__device__ float4 g_cee[TOTMAX];           // CSR-ordered exp weights (per head)
__device__ float  g_pool[GRAPHS * HC];     // per-graph sums [G,256]
__device__ float  g_cnt[GRAPHS];           // per-graph node counts

// ---------------- 0: init scratch ----------------
__global__ void init_kernel(int M) {
    int i = blockIdx.x * blockDim.x + threadIdx.x;
    if (i < M)            g_count[i] = 1;   // self-loop pre-counted
    if (i < GRAPHS * HC)  g_pool[i]  = 0.0f;
    if (i < GRAPHS)       g_cnt[i]   = 0.0f;
}

// ---------------- 1: h = x @ lin_w (+ fused att dots) + free-rider edge count ----------
// GEMM blocks: bx in {0,1}, 128x128 tile, BK=8, 256 threads, 8x8/thread. [R6-proven]
// Count blocks: bx == 2 do grid-stride degree counting (memory-bound, rides free
// under the compute-bound GEMM).
#define BM 128
#define BN 128
#define BK 8
__global__ __launch_bounds__(256, 2)
void gemm_h_kernel(const float* __restrict__ X,
                   const float* __restrict__ W,
                   const float* __restrict__ att_s,
                   const float* __restrict__ att_d,
                   const int* __restrict__ ei,
                   int M, int E) {
    const int bx   = blockIdx.x;
    const int tid  = threadIdx.x;

    if (bx == 2) {   // -------- edge-count role --------
        int stride = gridDim.y * blockDim.x;
        for (int i = blockIdx.y * blockDim.x + tid; i < E; i += stride)
            atomicAdd(&g_count[ei[E + i]], 1);
        return;
    }

    __shared__ float As[BK][BM];
    __shared__ float Bs[BK][BN];
    __shared__ float s_as[BN], s_ad[BN];

    const int row0 = blockIdx.y * BM;
    const int tx   = tid & 15;
    const int ty   = tid >> 4;

    if (tid < BN) { s_as[tid] = att_s[bx * BN + tid]; s_ad[tid] = att_d[bx * BN + tid]; }

    float acc[2][2][4][4];
#pragma unroll
    for (int a = 0; a < 2; a++)
#pragma unroll
        for (int b = 0; b < 2; b++)
#pragma unroll
            for (int i = 0; i < 4; i++)
#pragma unroll
                for (int j = 0; j < 4; j++) acc[a][b][i][j] = 0.0f;

    const int arow  = tid >> 1;             // 0..127
    const int akb   = (tid & 1) * 4;        // 0 or 4
    const int bkk   = tid >> 5;             // 0..7
    const int bcol  = (tid & 31) * 4;       // 0..124

    for (int k0 = 0; k0 < KIN; k0 += BK) {
        {
            int gr = row0 + arow, gk = k0 + akb;
            float4 a4 = make_float4(0.f, 0.f, 0.f, 0.f);
            if (gr < M && gk < KIN) a4 = *(const float4*)&X[gr * KIN + gk];
            As[akb + 0][arow] = a4.x;
            As[akb + 1][arow] = a4.y;
            As[akb + 2][arow] = a4.z;
            As[akb + 3][arow] = a4.w;
        }
        {
            int gk = k0 + bkk;
            float4 b4 = make_float4(0.f, 0.f, 0.f, 0.f);
            if (gk < KIN) b4 = *(const float4*)&W[gk * HC + bx * BN + bcol];
            *(float4*)&Bs[bkk][bcol] = b4;
        }
        __syncthreads();
#pragma unroll
        for (int kk = 0; kk < BK; kk++) {
            float4 a0 = *(const float4*)&As[kk][ty * 4];
            float4 a1 = *(const float4*)&As[kk][64 + ty * 4];
            float4 b0 = *(const float4*)&Bs[kk][tx * 4];
            float4 b1 = *(const float4*)&Bs[kk][64 + tx * 4];
            float av[2][4] = {{a0.x, a0.y, a0.z, a0.w}, {a1.x, a1.y, a1.z, a1.w}};
            float bv[2][4] = {{b0.x, b0.y, b0.z, b0.w}, {b1.x, b1.y, b1.z, b1.w}};
#pragma unroll
            for (int a = 0; a < 2; a++)
#pragma unroll
                for (int b = 0; b < 2; b++)
#pragma unroll
                    for (int i = 0; i < 4; i++)
#pragma unroll
                        for (int j = 0; j < 4; j++)
                            acc[a][b][i][j] += av[a][i] * bv[b][j];
        }
        __syncthreads();
    }

    // epilogue: store h + fused attention dots
#pragma unroll
    for (int a = 0; a < 2; a++) {
#pragma unroll
        for (int i = 0; i < 4; i++) {
            int gr = row0 + a * 64 + ty * 4 + i;
            bool ok = gr < M;
#pragma unroll
            for (int b = 0; b < 2; b++) {
                if (ok) {
                    *(float4*)&g_h[gr * HC + bx * BN + b * 64 + tx * 4] =
                        make_float4(acc[a][b][i][0], acc[a][b][i][1],
                                    acc[a][b][i][2], acc[a][b][i][3]);
                }
                float s = 0.f, d = 0.f;
#pragma unroll
                for (int j = 0; j < 4; j++) {
                    s += acc[a][b][i][j] * s_as[b * 64 + tx * 4 + j];
                    d += acc[a][b][i][j] * s_ad[b * 64 + tx * 4 + j];
                }
#pragma unroll
                for (int off = 8; off > 0; off >>= 1) {
                    s += __shfl_down_sync(0xffffffffu, s, off, 16);
                    d += __shfl_down_sync(0xffffffffu, d, off, 16);
                }
                if (ok && tx == 0) {
                    g_asrc[gr * 4 + bx * 2 + b] = s;
                    g_adst[gr * 4 + bx * 2 + b] = d;
                }
            }
        }
    }
}

// ---------------- 3: 2-level exclusive scan of g_count ----------------
__global__ void scan1_kernel(int M) {                     // block=1024
    __shared__ int sh[2][1024];
    int i = blockIdx.x * 1024 + threadIdx.x;
    int v = (i < M) ? g_count[i] : 0;
    int buf = 0;
    sh[0][threadIdx.x] = v;
    __syncthreads();
#pragma unroll
    for (int off = 1; off < 1024; off <<= 1) {
        int nv = sh[buf][threadIdx.x];
        if (threadIdx.x >= off) nv += sh[buf][threadIdx.x - off];
        sh[1 - buf][threadIdx.x] = nv;
        buf = 1 - buf;
        __syncthreads();
    }
    int incl = sh[buf][threadIdx.x];
    if (i < M) g_scanex[i] = incl - v;
    if (threadIdx.x == 1023) g_bsum[blockIdx.x] = incl;
}

__global__ void scan2_kernel(int nb) {                    // 1 block of 64 threads
    __shared__ int sh[2][64];
    int t = threadIdx.x;
    int v = (t < nb) ? g_bsum[t] : 0;
    int buf = 0;
    sh[0][t] = v;
    __syncthreads();
#pragma unroll
    for (int off = 1; off < 64; off <<= 1) {
        int nv = sh[buf][t];
        if (t >= off) nv += sh[buf][t - off];
        sh[1 - buf][t] = nv;
        buf = 1 - buf;
        __syncthreads();
    }
    if (t < nb) g_bsum[t] = sh[buf][t] - v;   // exclusive
}

__global__ void scan3_kernel(int M) {
    int i = blockIdx.x * blockDim.x + threadIdx.x;
    if (i >= M) return;
    int off = g_scanex[i] + g_bsum[i >> 10];
    g_rowoff[i] = off;
    g_cursor[i] = off;
}

// ---------------- 4: CSR fill (recomputes leaky+exp) ----------------
__global__ void edge_fill_kernel(const int* __restrict__ ei, int E, int M) {
    int i = blockIdx.x * blockDim.x + threadIdx.x;
    int total = E + M;
    if (i >= total) return;
    int s, d;
    if (i < E) { s = ei[i]; d = ei[E + i]; }
    else       { s = d = i - E; }
    float4 as = ((const float4*)g_asrc)[s];
    float4 ad = ((const float4*)g_adst)[d];
    float e0 = as.x + ad.x, e1 = as.y + ad.y, e2 = as.z + ad.z, e3 = as.w + ad.w;
    e0 = e0 > 0.f ? e0 : 0.2f * e0;
    e1 = e1 > 0.f ? e1 : 0.2f * e1;
    e2 = e2 > 0.f ? e2 : 0.2f * e2;
    e3 = e3 > 0.f ? e3 : 0.2f * e3;
    float4 ee = make_float4(__expf(e0), __expf(e1), __expf(e2), __expf(e3));
    int pos = atomicAdd(&g_cursor[d], 1);
    g_csrc[pos] = s;
    g_cee[pos]  = ee;
}

// ---------------- 5: gather-aggregate (warp per node) + denom + bias + leaky + pool ----------------
__global__ void aggregate_kernel(const int* __restrict__ batch,
                                 const float* __restrict__ bias, int M) {
    int w = blockIdx.x * (blockDim.x >> 5) + (threadIdx.x >> 5);
    if (w >= M) return;
    int lane = threadIdx.x & 31;
    int start = g_rowoff[w];
    int end   = start + g_count[w];
    int hsel  = lane >> 3;                      // head for this thread's 8 channels

    float acc[8];
#pragma unroll
    for (int k = 0; k < 8; k++) acc[k] = 0.0f;
    float wsum = 0.0f;

    int src = 0; float4 ee = make_float4(0, 0, 0, 0);
    if (start < end) { src = g_csrc[start]; ee = g_cee[start]; }
    for (int j = start; j < end; j++) {
        int nsrc = 0; float4 nee = ee;
        if (j + 1 < end) { nsrc = g_csrc[j + 1]; nee = g_cee[j + 1]; }
        const float4* hp = (const float4*)&g_h[(long long)src * HC + lane * 8];
        float4 h0 = hp[0], h1 = hp[1];
        float wgt = (hsel == 0) ? ee.x : (hsel == 1) ? ee.y : (hsel == 2) ? ee.z : ee.w;
        wsum += wgt;
        acc[0] += h0.x * wgt; acc[1] += h0.y * wgt;
        acc[2] += h0.z * wgt; acc[3] += h0.w * wgt;
        acc[4] += h1.x * wgt; acc[5] += h1.y * wgt;
        acc[6] += h1.z * wgt; acc[7] += h1.w * wgt;
        src = nsrc; ee = nee;
    }

    float inv = 1.0f / wsum;
    int b = batch[w];
    float* pp = &g_pool[b * HC + lane * 8];
#pragma unroll
    for (int k = 0; k < 8; k++) {
        float v = acc[k] * inv + bias[lane * 8 + k];
        v = v > 0.f ? v : 0.01f * v;
        atomicAdd(&pp[k], v);
    }
    if (lane == 0) atomicAdd(&g_cnt[b], 1.0f);
}

// ---------------- 6: out = meanpool @ fc1_w + fc1_b (norm fused into load) ----------------
#define FBM 32
#define FBN 64
#define SPP 260
__global__ __launch_bounds__(256)
void fc_kernel(const float* __restrict__ fc1_w,
               const float* __restrict__ fc1_b,
               float* __restrict__ out) {
    __shared__ float sp[FBM * SPP];
    __shared__ float sw[32][FBN];
    __shared__ float sinv[FBM];
    const int g0  = blockIdx.y * FBM;
    const int n0  = blockIdx.x * FBN;
    const int tid = threadIdx.x;

    if (tid < FBM) sinv[tid] = 1.0f / fmaxf(g_cnt[g0 + tid], 1.0f);
    __syncthreads();

#pragma unroll
    for (int it = 0; it < 8; it++) {
        int i = tid + it * 256;
        int r = i >> 6;
        int c = (i & 63) * 4;
        float4 v = *(const float4*)&g_pool[(g0 + r) * HC + c];
        float inv = sinv[r];
        *(float4*)&sp[r * SPP + c] = make_float4(v.x * inv, v.y * inv, v.z * inv, v.w * inv);
    }

    const int row = tid >> 3;
    const int cg  = (tid & 7) * 8;
    float acc[8];
#pragma unroll
    for (int j = 0; j < 8; j++) acc[j] = 0.0f;

    for (int k0 = 0; k0 < HC; k0 += 32) {
        __syncthreads();
#pragma unroll
        for (int it = 0; it < 2; it++) {
            int i = tid + it * 256;
            int r = i >> 4;
            int c = (i & 15) * 4;
            *(float4*)&sw[r][c] = *(const float4*)&fc1_w[(k0 + r) * FOUT + n0 + c];
        }
        __syncthreads();
#pragma unroll
        for (int kk = 0; kk < 32; kk++) {
            float p = sp[row * SPP + k0 + kk];
            float4 w0 = *(const float4*)&sw[kk][cg];
            float4 w1 = *(const float4*)&sw[kk][cg + 4];
            acc[0] += p * w0.x; acc[1] += p * w0.y;
            acc[2] += p * w0.z; acc[3] += p * w0.w;
            acc[4] += p * w1.x; acc[5] += p * w1.y;
            acc[6] += p * w1.z; acc[7] += p * w1.w;
        }
    }
#pragma unroll
    for (int j = 0; j < 8; j++) acc[j] += fc1_b[n0 + cg + j];
    *(float4*)&out[(g0 + row) * FOUT + n0 + cg]     = make_float4(acc[0], acc[1], acc[2], acc[3]);
    *(float4*)&out[(g0 + row) * FOUT + n0 + cg + 4] = make_float4(acc[4], acc[5], acc[6], acc[7]);
}

// ---------------- launch ----------------
extern "C" void kernel_launch(void* const* d_in, const int* in_sizes, int n_in,
                              void* d_out, int out_size) {
    const float* x     = (const float*)d_in[0];
    const int*   ei    = (const int*)d_in[1];
    const int*   batch = (const int*)d_in[2];
    const float* lin_w = (const float*)d_in[3];
    const float* att_s = (const float*)d_in[4];
    const float* att_d = (const float*)d_in[5];
    const float* bias  = (const float*)d_in[6];
    const float* fc1_w = (const float*)d_in[7];
    const float* fc1_b = (const float*)d_in[8];
    float* out = (float*)d_out;

    int M = in_sizes[2];       // nodes
    int E = in_sizes[1] / 2;   // edges
    int total = E + M;

    int initN = M > GRAPHS * HC ? M : GRAPHS * HC;
    init_kernel<<<(initN + 255) / 256, 256>>>(M);

    // GEMM (bx 0,1) + free-rider edge count (bx 2)
    dim3 ggrid(3, (M + BM - 1) / BM);
    gemm_h_kernel<<<ggrid, 256>>>(x, lin_w, att_s, att_d, ei, M, E);

    int nb = (M + 1023) / 1024;
    scan1_kernel<<<nb, 1024>>>(M);
    scan2_kernel<<<1, 64>>>(nb);
    scan3_kernel<<<(M + 255) / 256, 256>>>(M);

    edge_fill_kernel<<<(total + 255) / 256, 256>>>(ei, E, M);

    aggregate_kernel<<<(M * 32 + 255) / 256, 256>>>(batch, bias, M);

    dim3 fgrid(FOUT / FBN, GRAPHS / FBM);
    fc_kernel<<<fgrid, 256>>>(fc1_w, fc1_b, out);
}

// round 10
// speedup vs baseline: 1.0482x; 1.0417x over previous
#include <cuda_runtime.h>
#include <cuda_bf16.h>

// Problem constants
#define NMAX   50000
#define EMAX   800000
#define TOTMAX (EMAX + NMAX)
#define GRAPHS 256
#define HC     256      // H*C
#define KIN    300      // n_in
#define FOUT   768      // nout

// ---------------- scratch (device globals; no allocation) ----------------
__device__ __nv_bfloat16 g_hb[NMAX * HC];  // node features after linear, bf16 [N,256]
__device__ float  g_asrc[NMAX * 4];        // per-node src attention logits [N,4] (fp32)
__device__ float  g_adst[NMAX * 4];        // per-node dst attention logits [N,4] (fp32)
__device__ int    g_count[NMAX];           // in-degree (incl self-loop)
__device__ int    g_scanex[NMAX];          // per-chunk exclusive scan
__device__ int    g_bsum[64];              // chunk totals -> chunk offsets
__device__ int    g_rowoff[NMAX];          // CSR row offsets
__device__ int    g_cursor[NMAX];          // fill cursors
__device__ int    g_csrc[TOTMAX];          // CSR-ordered src ids
__device__ float4 g_cee[TOTMAX];           // CSR-ordered exp weights (per head)
__device__ float  g_pool[GRAPHS * HC];     // per-graph sums [G,256]
__device__ float  g_cnt[GRAPHS];           // per-graph node counts

// ---------------- 0: init scratch ----------------
__global__ void init_kernel(int M) {
    int i = blockIdx.x * blockDim.x + threadIdx.x;
    if (i < M)            g_count[i] = 1;   // self-loop pre-counted
    if (i < GRAPHS * HC)  g_pool[i]  = 0.0f;
    if (i < GRAPHS)       g_cnt[i]   = 0.0f;
}

// ---------------- 1: degree count (dst only; self-loops pre-counted) ----------------
__global__ void edge_count_kernel(const int* __restrict__ ei, int E) {
    int i = blockIdx.x * blockDim.x + threadIdx.x;
    if (i >= E) return;
    atomicAdd(&g_count[ei[E + i]], 1);
}

// ---------------- 2: 2-level exclusive scan of g_count ----------------
__global__ void scan1_kernel(int M) {                     // block=1024
    __shared__ int sh[2][1024];
    int i = blockIdx.x * 1024 + threadIdx.x;
    int v = (i < M) ? g_count[i] : 0;
    int buf = 0;
    sh[0][threadIdx.x] = v;
    __syncthreads();
#pragma unroll
    for (int off = 1; off < 1024; off <<= 1) {
        int nv = sh[buf][threadIdx.x];
        if (threadIdx.x >= off) nv += sh[buf][threadIdx.x - off];
        sh[1 - buf][threadIdx.x] = nv;
        buf = 1 - buf;
        __syncthreads();
    }
    int incl = sh[buf][threadIdx.x];
    if (i < M) g_scanex[i] = incl - v;
    if (threadIdx.x == 1023) g_bsum[blockIdx.x] = incl;
}

// ---------------- 3: GEMM h = x @ lin_w (+ fused att dots), fp32 SIMT, bf16 out ----
// 128x128 tile, BK=8, 256 threads, 8x8 per thread. [R6-proven body]
#define BM 128
#define BN 128
#define BK 8
__global__ __launch_bounds__(256, 2)
void gemm_h_kernel(const float* __restrict__ X,
                   const float* __restrict__ W,
                   const float* __restrict__ att_s,
                   const float* __restrict__ att_d,
                   int M) {
    __shared__ float As[BK][BM];
    __shared__ float Bs[BK][BN];
    __shared__ float s_as[BN], s_ad[BN];

    const int bx   = blockIdx.x;              // 0..1 -> N offset bx*128 (heads bx*2, bx*2+1)
    const int row0 = blockIdx.y * BM;
    const int tid  = threadIdx.x;
    const int tx   = tid & 15;
    const int ty   = tid >> 4;

    if (tid < BN) { s_as[tid] = att_s[bx * BN + tid]; s_ad[tid] = att_d[bx * BN + tid]; }

    float acc[2][2][4][4];
#pragma unroll
    for (int a = 0; a < 2; a++)
#pragma unroll
        for (int b = 0; b < 2; b++)
#pragma unroll
            for (int i = 0; i < 4; i++)
#pragma unroll
                for (int j = 0; j < 4; j++) acc[a][b][i][j] = 0.0f;

    const int arow  = tid >> 1;             // 0..127
    const int akb   = (tid & 1) * 4;        // 0 or 4
    const int bkk   = tid >> 5;             // 0..7
    const int bcol  = (tid & 31) * 4;       // 0..124

    for (int k0 = 0; k0 < KIN; k0 += BK) {
        {
            int gr = row0 + arow, gk = k0 + akb;
            float4 a4 = make_float4(0.f, 0.f, 0.f, 0.f);
            if (gr < M && gk < KIN) a4 = *(const float4*)&X[gr * KIN + gk];
            As[akb + 0][arow] = a4.x;
            As[akb + 1][arow] = a4.y;
            As[akb + 2][arow] = a4.z;
            As[akb + 3][arow] = a4.w;
        }
        {
            int gk = k0 + bkk;
            float4 b4 = make_float4(0.f, 0.f, 0.f, 0.f);
            if (gk < KIN) b4 = *(const float4*)&W[gk * HC + bx * BN + bcol];
            *(float4*)&Bs[bkk][bcol] = b4;
        }
        __syncthreads();
#pragma unroll
        for (int kk = 0; kk < BK; kk++) {
            float4 a0 = *(const float4*)&As[kk][ty * 4];
            float4 a1 = *(const float4*)&As[kk][64 + ty * 4];
            float4 b0 = *(const float4*)&Bs[kk][tx * 4];
            float4 b1 = *(const float4*)&Bs[kk][64 + tx * 4];
            float av[2][4] = {{a0.x, a0.y, a0.z, a0.w}, {a1.x, a1.y, a1.z, a1.w}};
            float bv[2][4] = {{b0.x, b0.y, b0.z, b0.w}, {b1.x, b1.y, b1.z, b1.w}};
#pragma unroll
            for (int a = 0; a < 2; a++)
#pragma unroll
                for (int b = 0; b < 2; b++)
#pragma unroll
                    for (int i = 0; i < 4; i++)
#pragma unroll
                        for (int j = 0; j < 4; j++)
                            acc[a][b][i][j] += av[a][i] * bv[b][j];
        }
        __syncthreads();
    }

    // epilogue: store h (bf16) + fused attention dots (fp32)
#pragma unroll
    for (int a = 0; a < 2; a++) {
#pragma unroll
        for (int i = 0; i < 4; i++) {
            int gr = row0 + a * 64 + ty * 4 + i;
            bool ok = gr < M;
#pragma unroll
            for (int b = 0; b < 2; b++) {
                if (ok) {
                    __nv_bfloat162 p0 = __float22bfloat162_rn(
                        make_float2(acc[a][b][i][0], acc[a][b][i][1]));
                    __nv_bfloat162 p1 = __float22bfloat162_rn(
                        make_float2(acc[a][b][i][2], acc[a][b][i][3]));
                    *(__nv_bfloat162*)&g_hb[(long long)gr * HC + bx * BN + b * 64 + tx * 4]     = p0;
                    *(__nv_bfloat162*)&g_hb[(long long)gr * HC + bx * BN + b * 64 + tx * 4 + 2] = p1;
                }
                float s = 0.f, d = 0.f;
#pragma unroll
                for (int j = 0; j < 4; j++) {
                    s += acc[a][b][i][j] * s_as[b * 64 + tx * 4 + j];
                    d += acc[a][b][i][j] * s_ad[b * 64 + tx * 4 + j];
                }
#pragma unroll
                for (int off = 8; off > 0; off >>= 1) {
                    s += __shfl_down_sync(0xffffffffu, s, off, 16);
                    d += __shfl_down_sync(0xffffffffu, d, off, 16);
                }
                if (ok && tx == 0) {
                    g_asrc[gr * 4 + bx * 2 + b] = s;
                    g_adst[gr * 4 + bx * 2 + b] = d;
                }
            }
        }
    }
}

// ---------------- 4: scan finish ----------------
__global__ void scan2_kernel(int nb) {                    // 1 block of 64 threads
    __shared__ int sh[2][64];
    int t = threadIdx.x;
    int v = (t < nb) ? g_bsum[t] : 0;
    int buf = 0;
    sh[0][t] = v;
    __syncthreads();
#pragma unroll
    for (int off = 1; off < 64; off <<= 1) {
        int nv = sh[buf][t];
        if (t >= off) nv += sh[buf][t - off];
        sh[1 - buf][t] = nv;
        buf = 1 - buf;
        __syncthreads();
    }
    if (t < nb) g_bsum[t] = sh[buf][t] - v;   // exclusive
}

__global__ void scan3_kernel(int M) {
    int i = blockIdx.x * blockDim.x + threadIdx.x;
    if (i >= M) return;
    int off = g_scanex[i] + g_bsum[i >> 10];
    g_rowoff[i] = off;
    g_cursor[i] = off;
}

// ---------------- 5: CSR fill (recomputes leaky+exp) ----------------
__global__ void edge_fill_kernel(const int* __restrict__ ei, int E, int M) {
    int i = blockIdx.x * blockDim.x + threadIdx.x;
    int total = E + M;
    if (i >= total) return;
    int s, d;
    if (i < E) { s = ei[i]; d = ei[E + i]; }
    else       { s = d = i - E; }
    float4 as = ((const float4*)g_asrc)[s];
    float4 ad = ((const float4*)g_adst)[d];
    float e0 = as.x + ad.x, e1 = as.y + ad.y, e2 = as.z + ad.z, e3 = as.w + ad.w;
    e0 = e0 > 0.f ? e0 : 0.2f * e0;
    e1 = e1 > 0.f ? e1 : 0.2f * e1;
    e2 = e2 > 0.f ? e2 : 0.2f * e2;
    e3 = e3 > 0.f ? e3 : 0.2f * e3;
    float4 ee = make_float4(__expf(e0), __expf(e1), __expf(e2), __expf(e3));
    int pos = atomicAdd(&g_cursor[d], 1);
    g_csrc[pos] = s;
    g_cee[pos]  = ee;
}

// ---------------- 6: gather-aggregate (warp per node, bf16 h) + pool ----------------
__global__ void aggregate_kernel(const int* __restrict__ batch,
                                 const float* __restrict__ bias, int M) {
    int w = blockIdx.x * (blockDim.x >> 5) + (threadIdx.x >> 5);
    if (w >= M) return;
    int lane = threadIdx.x & 31;
    int start = g_rowoff[w];
    int end   = start + g_count[w];
    int hsel  = lane >> 3;                      // head for this thread's 8 channels

    float acc[8];
#pragma unroll
    for (int k = 0; k < 8; k++) acc[k] = 0.0f;
    float wsum = 0.0f;

    int src = 0; float4 ee = make_float4(0, 0, 0, 0);
    if (start < end) { src = g_csrc[start]; ee = g_cee[start]; }
    for (int j = start; j < end; j++) {
        int nsrc = 0; float4 nee = ee;
        if (j + 1 < end) { nsrc = g_csrc[j + 1]; nee = g_cee[j + 1]; }
        uint4 hv = *(const uint4*)&g_hb[(long long)src * HC + lane * 8];
        float2 p0 = __bfloat1622float2(*(const __nv_bfloat162*)&hv.x);
        float2 p1 = __bfloat1622float2(*(const __nv_bfloat162*)&hv.y);
        float2 p2 = __bfloat1622float2(*(const __nv_bfloat162*)&hv.z);
        float2 p3 = __bfloat1622float2(*(const __nv_bfloat162*)&hv.w);
        float wgt = (hsel == 0) ? ee.x : (hsel == 1) ? ee.y : (hsel == 2) ? ee.z : ee.w;
        wsum += wgt;
        acc[0] += p0.x * wgt; acc[1] += p0.y * wgt;
        acc[2] += p1.x * wgt; acc[3] += p1.y * wgt;
        acc[4] += p2.x * wgt; acc[5] += p2.y * wgt;
        acc[6] += p3.x * wgt; acc[7] += p3.y * wgt;
        src = nsrc; ee = nee;
    }

    float inv = 1.0f / wsum;
    int b = batch[w];
    float* pp = &g_pool[b * HC + lane * 8];
#pragma unroll
    for (int k = 0; k < 8; k++) {
        float v = acc[k] * inv + bias[lane * 8 + k];
        v = v > 0.f ? v : 0.01f * v;
        atomicAdd(&pp[k], v);
    }
    if (lane == 0) atomicAdd(&g_cnt[b], 1.0f);
}

// ---------------- 7: out = meanpool @ fc1_w + fc1_b (norm fused into load) ----------------
#define FBM 32
#define FBN 64
#define SPP 260
__global__ __launch_bounds__(256)
void fc_kernel(const float* __restrict__ fc1_w,
               const float* __restrict__ fc1_b,
               float* __restrict__ out) {
    __shared__ float sp[FBM * SPP];
    __shared__ float sw[32][FBN];
    __shared__ float sinv[FBM];
    const int g0  = blockIdx.y * FBM;
    const int n0  = blockIdx.x * FBN;
    const int tid = threadIdx.x;

    if (tid < FBM) sinv[tid] = 1.0f / fmaxf(g_cnt[g0 + tid], 1.0f);
    __syncthreads();

#pragma unroll
    for (int it = 0; it < 8; it++) {
        int i = tid + it * 256;
        int r = i >> 6;
        int c = (i & 63) * 4;
        float4 v = *(const float4*)&g_pool[(g0 + r) * HC + c];
        float inv = sinv[r];
        *(float4*)&sp[r * SPP + c] = make_float4(v.x * inv, v.y * inv, v.z * inv, v.w * inv);
    }

    const int row = tid >> 3;
    const int cg  = (tid & 7) * 8;
    float acc[8];
#pragma unroll
    for (int j = 0; j < 8; j++) acc[j] = 0.0f;

    for (int k0 = 0; k0 < HC; k0 += 32) {
        __syncthreads();
#pragma unroll
        for (int it = 0; it < 2; it++) {
            int i = tid + it * 256;
            int r = i >> 4;
            int c = (i & 15) * 4;
            *(float4*)&sw[r][c] = *(const float4*)&fc1_w[(k0 + r) * FOUT + n0 + c];
        }
        __syncthreads();
#pragma unroll
        for (int kk = 0; kk < 32; kk++) {
            float p = sp[row * SPP + k0 + kk];
            float4 w0 = *(const float4*)&sw[kk][cg];
            float4 w1 = *(const float4*)&sw[kk][cg + 4];
            acc[0] += p * w0.x; acc[1] += p * w0.y;
            acc[2] += p * w0.z; acc[3] += p * w0.w;
            acc[4] += p * w1.x; acc[5] += p * w1.y;
            acc[6] += p * w1.z; acc[7] += p * w1.w;
        }
    }
#pragma unroll
    for (int j = 0; j < 8; j++) acc[j] += fc1_b[n0 + cg + j];
    *(float4*)&out[(g0 + row) * FOUT + n0 + cg]     = make_float4(acc[0], acc[1], acc[2], acc[3]);
    *(float4*)&out[(g0 + row) * FOUT + n0 + cg + 4] = make_float4(acc[4], acc[5], acc[6], acc[7]);
}

// ---------------- launch ----------------
extern "C" void kernel_launch(void* const* d_in, const int* in_sizes, int n_in,
                              void* d_out, int out_size) {
    const float* x     = (const float*)d_in[0];
    const int*   ei    = (const int*)d_in[1];
    const int*   batch = (const int*)d_in[2];
    const float* lin_w = (const float*)d_in[3];
    const float* att_s = (const float*)d_in[4];
    const float* att_d = (const float*)d_in[5];
    const float* bias  = (const float*)d_in[6];
    const float* fc1_w = (const float*)d_in[7];
    const float* fc1_b = (const float*)d_in[8];
    float* out = (float*)d_out;

    int M = in_sizes[2];       // nodes
    int E = in_sizes[1] / 2;   // edges
    int total = E + M;

    int initN = M > GRAPHS * HC ? M : GRAPHS * HC;
    init_kernel<<<(initN + 255) / 256, 256>>>(M);              // 0

    edge_count_kernel<<<(E + 255) / 256, 256>>>(ei, E);        // 1

    int nb = (M + 1023) / 1024;
    scan1_kernel<<<nb, 1024>>>(M);                             // 2

    dim3 ggrid(2, (M + BM - 1) / BM);
    gemm_h_kernel<<<ggrid, 256>>>(x, lin_w, att_s, att_d, M);  // 3 <- ncu capture slot

    scan2_kernel<<<1, 64>>>(nb);                               // 4
    scan3_kernel<<<(M + 255) / 256, 256>>>(M);                 // 5

    edge_fill_kernel<<<(total + 255) / 256, 256>>>(ei, E, M);  // 6

    aggregate_kernel<<<(M * 32 + 255) / 256, 256>>>(batch, bias, M);  // 7

    dim3 fgrid(FOUT / FBN, GRAPHS / FBM);
    fc_kernel<<<fgrid, 256>>>(fc1_w, fc1_b, out);              // 8
}

// round 11
// speedup vs baseline: 1.4733x; 1.4055x over previous
#include <cuda_runtime.h>
#include <cuda_bf16.h>
#include <mma.h>
using namespace nvcuda;

// Problem constants
#define NMAX   50000
#define EMAX   800000
#define TOTMAX (EMAX + NMAX)
#define GRAPHS 256
#define HC     256      // H*C
#define KIN    300      // n_in
#define KPAD   320      // padded K for bf16 GEMM
#define FOUT   768      // nout

// ---------------- scratch (device globals; no allocation) ----------------
__device__ __nv_bfloat16 g_xb[NMAX * KPAD]; // bf16 X, K padded with zeros
__device__ __nv_bfloat16 g_wb[KPAD * HC];   // bf16 W, K padded with zeros
__device__ __nv_bfloat16 g_hb[NMAX * HC];   // node features after linear, bf16 [N,256]
__device__ float  g_asrc[NMAX * 4];         // per-node src attention logits [N,4] (fp32)
__device__ float  g_adst[NMAX * 4];         // per-node dst attention logits [N,4] (fp32)
__device__ int    g_count[NMAX];            // in-degree (incl self-loop)
__device__ int    g_scanex[NMAX];           // per-chunk exclusive scan
__device__ int    g_bsum[64];               // chunk totals -> chunk offsets
__device__ int    g_rowoff[NMAX];           // CSR row offsets
__device__ int    g_cursor[NMAX];           // fill cursors
__device__ int    g_csrc[TOTMAX];           // CSR-ordered src ids
__device__ float  g_pool[GRAPHS * HC];      // per-graph sums [G,256]
__device__ float  g_cnt[GRAPHS];            // per-graph node counts

// ---------------- 0: init scratch ----------------
__global__ void init_kernel(int M) {
    int i = blockIdx.x * blockDim.x + threadIdx.x;
    if (i < M)            g_count[i] = 1;   // self-loop pre-counted
    if (i < GRAPHS * HC)  g_pool[i]  = 0.0f;
    if (i < GRAPHS)       g_cnt[i]   = 0.0f;
}

// ---------------- 1: convert X, W to bf16 (K padded to 320) ----------------
__global__ void convert_kernel(const float* __restrict__ X,
                               const float* __restrict__ W, int M) {
    int i = blockIdx.x * blockDim.x + threadIdx.x;
    // X part: M rows x 80 float4-chunks (KPAD/4)
    if (i < M * (KPAD / 4)) {
        int row = i / (KPAD / 4);
        int c4  = (i % (KPAD / 4)) * 4;
        float4 v = make_float4(0.f, 0.f, 0.f, 0.f);
        if (c4 < KIN) v = *(const float4*)&X[row * KIN + c4];   // KIN divisible by 4
        __nv_bfloat162 p0 = __float22bfloat162_rn(make_float2(v.x, v.y));
        __nv_bfloat162 p1 = __float22bfloat162_rn(make_float2(v.z, v.w));
        *(__nv_bfloat162*)&g_xb[row * KPAD + c4]     = p0;
        *(__nv_bfloat162*)&g_xb[row * KPAD + c4 + 2] = p1;
    }
    // W part: KPAD rows x 64 float4-chunks
    if (i < KPAD * (HC / 4)) {
        int row = i / (HC / 4);
        int c4  = (i % (HC / 4)) * 4;
        float4 v = make_float4(0.f, 0.f, 0.f, 0.f);
        if (row < KIN) v = *(const float4*)&W[row * HC + c4];
        __nv_bfloat162 p0 = __float22bfloat162_rn(make_float2(v.x, v.y));
        __nv_bfloat162 p1 = __float22bfloat162_rn(make_float2(v.z, v.w));
        *(__nv_bfloat162*)&g_wb[row * HC + c4]     = p0;
        *(__nv_bfloat162*)&g_wb[row * HC + c4 + 2] = p1;
    }
}

// ---------------- 2: degree count (dst only; self-loops pre-counted) ----------------
__global__ void edge_count_kernel(const int* __restrict__ ei, int E) {
    int i = blockIdx.x * blockDim.x + threadIdx.x;
    if (i >= E) return;
    atomicAdd(&g_count[ei[E + i]], 1);
}

// ---------------- 3: h = xb @ wb via bf16 wmma (+ fused att dots) ----------------
// Block 128x128, BKW=32 (2 k16 steps), 8 warps (4x2), warp tile 32x64.
#define BM 128
#define BKW 32
#define KP 40     // A smem stride (bf16), 80B rows
#define NP 136    // B smem stride (bf16), 272B rows
// smem: Ab[128*KP*2]=10240 | Bb[32*NP*2]=8704 -> 18944; staging 8*16*68*4=34816
#define SMRAW 34816
__global__ __launch_bounds__(256)
void gemm_h_kernel(const float* __restrict__ att_s,
                   const float* __restrict__ att_d,
                   int M) {
    __shared__ __align__(16) unsigned char smem_raw[SMRAW];
    __shared__ float s_as[128], s_ad[128];

    __nv_bfloat16* Ab = (__nv_bfloat16*)(smem_raw);
    __nv_bfloat16* Bb = (__nv_bfloat16*)(smem_raw + 10240);

    const int bx   = blockIdx.x;          // 0..1 -> N offset bx*128
    const int row0 = blockIdx.y * BM;
    const int tid  = threadIdx.x;
    const int warp = tid >> 5;
    const int lane = tid & 31;
    const int wm   = warp >> 1;           // 0..3 (M: wm*32)
    const int wn   = warp & 1;            // 0..1 (N: wn*64)

    if (tid < 128) { s_as[tid] = att_s[bx * 128 + tid]; s_ad[tid] = att_d[bx * 128 + tid]; }

    wmma::fragment<wmma::accumulator, 16, 16, 16, float> acc[2][4];
#pragma unroll
    for (int mt = 0; mt < 2; mt++)
#pragma unroll
        for (int nt = 0; nt < 4; nt++) wmma::fill_fragment(acc[mt][nt], 0.0f);

    for (int c = 0; c < KPAD / BKW; c++) {          // 10 chunks
        const int k0 = c * BKW;
        // A tile: 128 rows x 32 bf16; 512 chunks of 8 bf16 (16B)
#pragma unroll
        for (int it = 0; it < 2; it++) {
            int q   = tid + it * 256;
            int row = q >> 2;
            int c8  = (q & 3) * 8;
            int gr  = row0 + row;
            uint4 v = make_uint4(0u, 0u, 0u, 0u);
            if (gr < M) v = *(const uint4*)&g_xb[(long long)gr * KPAD + k0 + c8];
            *(uint4*)&Ab[row * KP + c8] = v;
        }
        // B tile: 32 k x 128 cols; 512 chunks of 8 bf16
#pragma unroll
        for (int it = 0; it < 2; it++) {
            int q  = tid + it * 256;
            int kk = q >> 4;
            int c8 = (q & 15) * 8;
            uint4 v = *(const uint4*)&g_wb[(k0 + kk) * HC + bx * 128 + c8];
            *(uint4*)&Bb[kk * NP + c8] = v;
        }
        __syncthreads();
#pragma unroll
        for (int ks = 0; ks < 2; ks++) {
            int kk16 = ks * 16;
            wmma::fragment<wmma::matrix_a, 16, 16, 16, __nv_bfloat16, wmma::row_major> af[2];
            wmma::fragment<wmma::matrix_b, 16, 16, 16, __nv_bfloat16, wmma::row_major> bf[4];
#pragma unroll
            for (int mt = 0; mt < 2; mt++)
                wmma::load_matrix_sync(af[mt], &Ab[(wm * 32 + mt * 16) * KP + kk16], KP);
#pragma unroll
            for (int nt = 0; nt < 4; nt++)
                wmma::load_matrix_sync(bf[nt], &Bb[kk16 * NP + wn * 64 + nt * 16], NP);
#pragma unroll
            for (int mt = 0; mt < 2; mt++)
#pragma unroll
                for (int nt = 0; nt < 4; nt++)
                    wmma::mma_sync(acc[mt][nt], af[mt], bf[nt], acc[mt][nt]);
        }
        __syncthreads();
    }

    // epilogue: per-warp staging, bf16 h store + fused fp32 att dots [R2-proven pattern]
    float* eb = (float*)smem_raw + warp * 16 * 68;
#pragma unroll
    for (int mt = 0; mt < 2; mt++) {
#pragma unroll
        for (int nt = 0; nt < 4; nt++)
            wmma::store_matrix_sync(&eb[nt * 16], acc[mt][nt], 68, wmma::mem_row_major);
        __syncwarp();
        int r   = lane >> 1;
        int chh = (lane & 1) * 32;
        int gr  = row0 + wm * 32 + mt * 16 + r;
        float s = 0.f, d = 0.f;
#pragma unroll
        for (int j = 0; j < 8; j++) {
            float4 v = *(float4*)&eb[r * 68 + chh + j * 4];
            int cb = wn * 64 + chh + j * 4;
            s += v.x * s_as[cb] + v.y * s_as[cb + 1] + v.z * s_as[cb + 2] + v.w * s_as[cb + 3];
            d += v.x * s_ad[cb] + v.y * s_ad[cb + 1] + v.z * s_ad[cb + 2] + v.w * s_ad[cb + 3];
            if (gr < M) {
                __nv_bfloat162 q0 = __float22bfloat162_rn(make_float2(v.x, v.y));
                __nv_bfloat162 q1 = __float22bfloat162_rn(make_float2(v.z, v.w));
                *(__nv_bfloat162*)&g_hb[(long long)gr * HC + bx * 128 + cb]     = q0;
                *(__nv_bfloat162*)&g_hb[(long long)gr * HC + bx * 128 + cb + 2] = q1;
            }
        }
        s += __shfl_xor_sync(0xffffffffu, s, 1);
        d += __shfl_xor_sync(0xffffffffu, d, 1);
        if ((lane & 1) == 0 && gr < M) {
            g_asrc[gr * 4 + bx * 2 + wn] = s;
            g_adst[gr * 4 + bx * 2 + wn] = d;
        }
        __syncwarp();
    }
}

// ---------------- 4: scan ----------------
__global__ void scan1_kernel(int M) {                     // block=1024
    __shared__ int sh[2][1024];
    int i = blockIdx.x * 1024 + threadIdx.x;
    int v = (i < M) ? g_count[i] : 0;
    int buf = 0;
    sh[0][threadIdx.x] = v;
    __syncthreads();
#pragma unroll
    for (int off = 1; off < 1024; off <<= 1) {
        int nv = sh[buf][threadIdx.x];
        if (threadIdx.x >= off) nv += sh[buf][threadIdx.x - off];
        sh[1 - buf][threadIdx.x] = nv;
        buf = 1 - buf;
        __syncthreads();
    }
    int incl = sh[buf][threadIdx.x];
    if (i < M) g_scanex[i] = incl - v;
    if (threadIdx.x == 1023) g_bsum[blockIdx.x] = incl;
}

__global__ void scan2_kernel(int nb) {                    // 1 block of 64 threads
    __shared__ int sh[2][64];
    int t = threadIdx.x;
    int v = (t < nb) ? g_bsum[t] : 0;
    int buf = 0;
    sh[0][t] = v;
    __syncthreads();
#pragma unroll
    for (int off = 1; off < 64; off <<= 1) {
        int nv = sh[buf][t];
        if (t >= off) nv += sh[buf][t - off];
        sh[1 - buf][t] = nv;
        buf = 1 - buf;
        __syncthreads();
    }
    if (t < nb) g_bsum[t] = sh[buf][t] - v;   // exclusive
}

__global__ void scan3_kernel(int M) {
    int i = blockIdx.x * blockDim.x + threadIdx.x;
    if (i >= M) return;
    int off = g_scanex[i] + g_bsum[i >> 10];
    g_rowoff[i] = off;
    g_cursor[i] = off;
}

// ---------------- 5: CSR fill (src ids only) ----------------
__global__ void edge_fill_kernel(const int* __restrict__ ei, int E, int M) {
    int i = blockIdx.x * blockDim.x + threadIdx.x;
    int total = E + M;
    if (i >= total) return;
    int s, d;
    if (i < E) { s = ei[i]; d = ei[E + i]; }
    else       { s = d = i - E; }
    int pos = atomicAdd(&g_cursor[d], 1);
    g_csrc[pos] = s;
}

// ---------------- 6: gather-aggregate (warp per node; ee recomputed) + pool ----------------
__global__ void aggregate_kernel(const int* __restrict__ batch,
                                 const float* __restrict__ bias, int M) {
    int w = blockIdx.x * (blockDim.x >> 5) + (threadIdx.x >> 5);
    if (w >= M) return;
    int lane = threadIdx.x & 31;
    int start = g_rowoff[w];
    int end   = start + g_count[w];
    int hsel  = lane >> 3;                      // head for this thread's 8 channels

    float4 ad4 = ((const float4*)g_adst)[w];
    float adh = (hsel == 0) ? ad4.x : (hsel == 1) ? ad4.y : (hsel == 2) ? ad4.z : ad4.w;

    float acc[8];
#pragma unroll
    for (int k = 0; k < 8; k++) acc[k] = 0.0f;
    float wsum = 0.0f;

    int src = 0;
    if (start < end) src = g_csrc[start];
    for (int j = start; j < end; j++) {
        int nsrc = src;
        if (j + 1 < end) nsrc = g_csrc[j + 1];
        float4 as4 = ((const float4*)g_asrc)[src];
        uint4 hv = *(const uint4*)&g_hb[(long long)src * HC + lane * 8];
        float ash = (hsel == 0) ? as4.x : (hsel == 1) ? as4.y : (hsel == 2) ? as4.z : as4.w;
        float e = ash + adh;
        e = e > 0.f ? e : 0.2f * e;
        float ee = __expf(e);
        wsum += ee;
        float2 p0 = __bfloat1622float2(*(const __nv_bfloat162*)&hv.x);
        float2 p1 = __bfloat1622float2(*(const __nv_bfloat162*)&hv.y);
        float2 p2 = __bfloat1622float2(*(const __nv_bfloat162*)&hv.z);
        float2 p3 = __bfloat1622float2(*(const __nv_bfloat162*)&hv.w);
        acc[0] += p0.x * ee; acc[1] += p0.y * ee;
        acc[2] += p1.x * ee; acc[3] += p1.y * ee;
        acc[4] += p2.x * ee; acc[5] += p2.y * ee;
        acc[6] += p3.x * ee; acc[7] += p3.y * ee;
        src = nsrc;
    }

    float inv = 1.0f / wsum;
    int b = batch[w];
    float* pp = &g_pool[b * HC + lane * 8];
#pragma unroll
    for (int k = 0; k < 8; k++) {
        float v = acc[k] * inv + bias[lane * 8 + k];
        v = v > 0.f ? v : 0.01f * v;
        atomicAdd(&pp[k], v);
    }
    if (lane == 0) atomicAdd(&g_cnt[b], 1.0f);
}

// ---------------- 7: out = meanpool @ fc1_w + fc1_b (norm fused into load) ----------------
#define FBM 32
#define FBN 64
#define SPP 260
__global__ __launch_bounds__(256)
void fc_kernel(const float* __restrict__ fc1_w,
               const float* __restrict__ fc1_b,
               float* __restrict__ out) {
    __shared__ float sp[FBM * SPP];
    __shared__ float sw[32][FBN];
    __shared__ float sinv[FBM];
    const int g0  = blockIdx.y * FBM;
    const int n0  = blockIdx.x * FBN;
    const int tid = threadIdx.x;

    if (tid < FBM) sinv[tid] = 1.0f / fmaxf(g_cnt[g0 + tid], 1.0f);
    __syncthreads();

#pragma unroll
    for (int it = 0; it < 8; it++) {
        int i = tid + it * 256;
        int r = i >> 6;
        int c = (i & 63) * 4;
        float4 v = *(const float4*)&g_pool[(g0 + r) * HC + c];
        float inv = sinv[r];
        *(float4*)&sp[r * SPP + c] = make_float4(v.x * inv, v.y * inv, v.z * inv, v.w * inv);
    }

    const int row = tid >> 3;
    const int cg  = (tid & 7) * 8;
    float acc[8];
#pragma unroll
    for (int j = 0; j < 8; j++) acc[j] = 0.0f;

    for (int k0 = 0; k0 < HC; k0 += 32) {
        __syncthreads();
#pragma unroll
        for (int it = 0; it < 2; it++) {
            int i = tid + it * 256;
            int r = i >> 4;
            int c = (i & 15) * 4;
            *(float4*)&sw[r][c] = *(const float4*)&fc1_w[(k0 + r) * FOUT + n0 + c];
        }
        __syncthreads();
#pragma unroll
        for (int kk = 0; kk < 32; kk++) {
            float p = sp[row * SPP + k0 + kk];
            float4 w0 = *(const float4*)&sw[kk][cg];
            float4 w1 = *(const float4*)&sw[kk][cg + 4];
            acc[0] += p * w0.x; acc[1] += p * w0.y;
            acc[2] += p * w0.z; acc[3] += p * w0.w;
            acc[4] += p * w1.x; acc[5] += p * w1.y;
            acc[6] += p * w1.z; acc[7] += p * w1.w;
        }
    }
#pragma unroll
    for (int j = 0; j < 8; j++) acc[j] += fc1_b[n0 + cg + j];
    *(float4*)&out[(g0 + row) * FOUT + n0 + cg]     = make_float4(acc[0], acc[1], acc[2], acc[3]);
    *(float4*)&out[(g0 + row) * FOUT + n0 + cg + 4] = make_float4(acc[4], acc[5], acc[6], acc[7]);
}

// ---------------- launch ----------------
extern "C" void kernel_launch(void* const* d_in, const int* in_sizes, int n_in,
                              void* d_out, int out_size) {
    const float* x     = (const float*)d_in[0];
    const int*   ei    = (const int*)d_in[1];
    const int*   batch = (const int*)d_in[2];
    const float* lin_w = (const float*)d_in[3];
    const float* att_s = (const float*)d_in[4];
    const float* att_d = (const float*)d_in[5];
    const float* bias  = (const float*)d_in[6];
    const float* fc1_w = (const float*)d_in[7];
    const float* fc1_b = (const float*)d_in[8];
    float* out = (float*)d_out;

    int M = in_sizes[2];       // nodes
    int E = in_sizes[1] / 2;   // edges
    int total = E + M;

    int initN = M > GRAPHS * HC ? M : GRAPHS * HC;
    init_kernel<<<(initN + 255) / 256, 256>>>(M);                      // 0

    int convN = M * (KPAD / 4);
    if (convN < KPAD * (HC / 4)) convN = KPAD * (HC / 4);
    convert_kernel<<<(convN + 255) / 256, 256>>>(x, lin_w, M);         // 1

    edge_count_kernel<<<(E + 255) / 256, 256>>>(ei, E);                // 2

    dim3 ggrid(2, (M + BM - 1) / BM);
    gemm_h_kernel<<<ggrid, 256>>>(att_s, att_d, M);                    // 3 <- ncu slot

    int nb = (M + 1023) / 1024;
    scan1_kernel<<<nb, 1024>>>(M);                                     // 4
    scan2_kernel<<<1, 64>>>(nb);                                       // 5
    scan3_kernel<<<(M + 255) / 256, 256>>>(M);                         // 6

    edge_fill_kernel<<<(total + 255) / 256, 256>>>(ei, E, M);          // 7

    aggregate_kernel<<<(M * 32 + 255) / 256, 256>>>(batch, bias, M);   // 8

    dim3 fgrid(FOUT / FBN, GRAPHS / FBM);
    fc_kernel<<<fgrid, 256>>>(fc1_w, fc1_b, out);                      // 9
}

// round 12
// speedup vs baseline: 1.5658x; 1.0628x over previous
#include <cuda_runtime.h>
#include <cuda_fp16.h>
#include <mma.h>
using namespace nvcuda;

// Problem constants
#define NMAX   50000
#define EMAX   800000
#define TOTMAX (EMAX + NMAX)
#define GRAPHS 256
#define HC     256      // H*C
#define KIN    300      // n_in
#define KPAD   320      // padded K for fp16 GEMM
#define FOUT   768      // nout

// ---------------- scratch (device globals; no allocation) ----------------
__device__ __half g_xh[NMAX * KPAD];  // fp16 X, K padded with zeros
__device__ __half g_wh[KPAD * HC];    // fp16 W, K padded with zeros
__device__ __half g_hh[NMAX * HC];    // node features after linear, fp16 [N,256]
__device__ float  g_asrc[NMAX * 4];   // per-node src attention logits [N,4] (fp32)
__device__ float  g_adst[NMAX * 4];   // per-node dst attention logits [N,4] (fp32)
__device__ int    g_count[NMAX];      // in-degree (incl self-loop)
__device__ int    g_scanex[NMAX];     // per-chunk exclusive scan
__device__ int    g_bsum[64];         // chunk totals -> chunk offsets
__device__ int    g_rowoff[NMAX];     // CSR row offsets
__device__ int    g_cursor[NMAX];     // fill cursors
__device__ int    g_csrc[TOTMAX];     // CSR-ordered src ids
__device__ float  g_pool[GRAPHS * HC];// per-graph sums [G,256]
__device__ float  g_cnt[GRAPHS];      // per-graph node counts

// ---------------- 0: init scratch ----------------
__global__ void init_kernel(int M) {
    int i = blockIdx.x * blockDim.x + threadIdx.x;
    if (i < M)            g_count[i] = 1;   // self-loop pre-counted
    if (i < GRAPHS * HC)  g_pool[i]  = 0.0f;
    if (i < GRAPHS)       g_cnt[i]   = 0.0f;
}

// ---------------- 1: convert X, W to fp16 (K padded to 320) ----------------
__global__ void convert_kernel(const float* __restrict__ X,
                               const float* __restrict__ W, int M) {
    int i = blockIdx.x * blockDim.x + threadIdx.x;
    if (i < M * (KPAD / 4)) {
        int row = i / (KPAD / 4);
        int c4  = (i % (KPAD / 4)) * 4;
        float4 v = make_float4(0.f, 0.f, 0.f, 0.f);
        if (c4 < KIN) v = *(const float4*)&X[row * KIN + c4];   // KIN divisible by 4
        *(__half2*)&g_xh[row * KPAD + c4]     = __float22half2_rn(make_float2(v.x, v.y));
        *(__half2*)&g_xh[row * KPAD + c4 + 2] = __float22half2_rn(make_float2(v.z, v.w));
    }
    if (i < KPAD * (HC / 4)) {
        int row = i / (HC / 4);
        int c4  = (i % (HC / 4)) * 4;
        float4 v = make_float4(0.f, 0.f, 0.f, 0.f);
        if (row < KIN) v = *(const float4*)&W[row * HC + c4];
        *(__half2*)&g_wh[row * HC + c4]     = __float22half2_rn(make_float2(v.x, v.y));
        *(__half2*)&g_wh[row * HC + c4 + 2] = __float22half2_rn(make_float2(v.z, v.w));
    }
}

// ---------------- 2: degree count (dst only; self-loops pre-counted) ----------------
__global__ void edge_count_kernel(const int* __restrict__ ei, int E) {
    int i = blockIdx.x * blockDim.x + threadIdx.x;
    if (i >= E) return;
    atomicAdd(&g_count[ei[E + i]], 1);
}

// ---------------- 3: h = xh @ wh via fp16 wmma (+ fused att dots) ----------------
// Block 128x128, BKW=64 (4 k16 steps), 8 warps (4x2), warp tile 32x64.
#define BM 128
#define BKW 64
#define KP 72     // A smem stride (half), 144B rows — ldmatrix conflict-free
#define NP 136    // B smem stride (half), 272B rows — ldmatrix conflict-free
// smem: Ah[128*72*2]=18432 | Bh[64*136*2]=17408 -> 35840; staging 8*16*68*4=34816 (reuse)
#define SMRAW 35840
__global__ __launch_bounds__(256)
void gemm_h_kernel(const float* __restrict__ att_s,
                   const float* __restrict__ att_d,
                   int M) {
    __shared__ __align__(16) unsigned char smem_raw[SMRAW];
    __shared__ float s_as[128], s_ad[128];

    __half* Ah = (__half*)(smem_raw);
    __half* Bh = (__half*)(smem_raw + 18432);

    const int bx   = blockIdx.x;          // 0..1 -> N offset bx*128
    const int row0 = blockIdx.y * BM;
    const int tid  = threadIdx.x;
    const int warp = tid >> 5;
    const int lane = tid & 31;
    const int wm   = warp >> 1;           // 0..3 (M: wm*32)
    const int wn   = warp & 1;            // 0..1 (N: wn*64)

    if (tid < 128) { s_as[tid] = att_s[bx * 128 + tid]; s_ad[tid] = att_d[bx * 128 + tid]; }

    wmma::fragment<wmma::accumulator, 16, 16, 16, float> acc[2][4];
#pragma unroll
    for (int mt = 0; mt < 2; mt++)
#pragma unroll
        for (int nt = 0; nt < 4; nt++) wmma::fill_fragment(acc[mt][nt], 0.0f);

    for (int c = 0; c < KPAD / BKW; c++) {          // 5 chunks
        const int k0 = c * BKW;
        // A tile: 128 rows x 64 half; 1024 chunks of 8 half (16B)
#pragma unroll
        for (int it = 0; it < 4; it++) {
            int q   = tid + it * 256;
            int row = q >> 3;
            int c8  = (q & 7) * 8;
            int gr  = row0 + row;
            uint4 v = make_uint4(0u, 0u, 0u, 0u);
            if (gr < M) v = *(const uint4*)&g_xh[(long long)gr * KPAD + k0 + c8];
            *(uint4*)&Ah[row * KP + c8] = v;
        }
        // B tile: 64 k x 128 cols; 1024 chunks of 8 half
#pragma unroll
        for (int it = 0; it < 4; it++) {
            int q  = tid + it * 256;
            int kk = q >> 4;
            int c8 = (q & 15) * 8;
            uint4 v = *(const uint4*)&g_wh[(k0 + kk) * HC + bx * 128 + c8];
            *(uint4*)&Bh[kk * NP + c8] = v;
        }
        __syncthreads();
#pragma unroll
        for (int ks = 0; ks < 4; ks++) {
            int kk16 = ks * 16;
            wmma::fragment<wmma::matrix_a, 16, 16, 16, __half, wmma::row_major> af[2];
            wmma::fragment<wmma::matrix_b, 16, 16, 16, __half, wmma::row_major> bf[4];
#pragma unroll
            for (int mt = 0; mt < 2; mt++)
                wmma::load_matrix_sync(af[mt], &Ah[(wm * 32 + mt * 16) * KP + kk16], KP);
#pragma unroll
            for (int nt = 0; nt < 4; nt++)
                wmma::load_matrix_sync(bf[nt], &Bh[kk16 * NP + wn * 64 + nt * 16], NP);
#pragma unroll
            for (int mt = 0; mt < 2; mt++)
#pragma unroll
                for (int nt = 0; nt < 4; nt++)
                    wmma::mma_sync(acc[mt][nt], af[mt], bf[nt], acc[mt][nt]);
        }
        __syncthreads();
    }

    // epilogue: per-warp staging, fp16 h store + fused fp32 att dots
    float* eb = (float*)smem_raw + warp * 16 * 68;
#pragma unroll
    for (int mt = 0; mt < 2; mt++) {
#pragma unroll
        for (int nt = 0; nt < 4; nt++)
            wmma::store_matrix_sync(&eb[nt * 16], acc[mt][nt], 68, wmma::mem_row_major);
        __syncwarp();
        int r   = lane >> 1;
        int chh = (lane & 1) * 32;
        int gr  = row0 + wm * 32 + mt * 16 + r;
        float s = 0.f, d = 0.f;
#pragma unroll
        for (int j = 0; j < 8; j++) {
            float4 v = *(float4*)&eb[r * 68 + chh + j * 4];
            int cb = wn * 64 + chh + j * 4;
            s += v.x * s_as[cb] + v.y * s_as[cb + 1] + v.z * s_as[cb + 2] + v.w * s_as[cb + 3];
            d += v.x * s_ad[cb] + v.y * s_ad[cb + 1] + v.z * s_ad[cb + 2] + v.w * s_ad[cb + 3];
            if (gr < M) {
                *(__half2*)&g_hh[(long long)gr * HC + bx * 128 + cb]     =
                    __float22half2_rn(make_float2(v.x, v.y));
                *(__half2*)&g_hh[(long long)gr * HC + bx * 128 + cb + 2] =
                    __float22half2_rn(make_float2(v.z, v.w));
            }
        }
        s += __shfl_xor_sync(0xffffffffu, s, 1);
        d += __shfl_xor_sync(0xffffffffu, d, 1);
        if ((lane & 1) == 0 && gr < M) {
            g_asrc[gr * 4 + bx * 2 + wn] = s;
            g_adst[gr * 4 + bx * 2 + wn] = d;
        }
        __syncwarp();
    }
}

// ---------------- 4: scan ----------------
__global__ void scan1_kernel(int M) {                     // block=1024
    __shared__ int sh[2][1024];
    int i = blockIdx.x * 1024 + threadIdx.x;
    int v = (i < M) ? g_count[i] : 0;
    int buf = 0;
    sh[0][threadIdx.x] = v;
    __syncthreads();
#pragma unroll
    for (int off = 1; off < 1024; off <<= 1) {
        int nv = sh[buf][threadIdx.x];
        if (threadIdx.x >= off) nv += sh[buf][threadIdx.x - off];
        sh[1 - buf][threadIdx.x] = nv;
        buf = 1 - buf;
        __syncthreads();
    }
    int incl = sh[buf][threadIdx.x];
    if (i < M) g_scanex[i] = incl - v;
    if (threadIdx.x == 1023) g_bsum[blockIdx.x] = incl;
}

__global__ void scan2_kernel(int nb) {                    // 1 block of 64 threads
    __shared__ int sh[2][64];
    int t = threadIdx.x;
    int v = (t < nb) ? g_bsum[t] : 0;
    int buf = 0;
    sh[0][t] = v;
    __syncthreads();
#pragma unroll
    for (int off = 1; off < 64; off <<= 1) {
        int nv = sh[buf][t];
        if (t >= off) nv += sh[buf][t - off];
        sh[1 - buf][t] = nv;
        buf = 1 - buf;
        __syncthreads();
    }
    if (t < nb) g_bsum[t] = sh[buf][t] - v;   // exclusive
}

__global__ void scan3_kernel(int M) {
    int i = blockIdx.x * blockDim.x + threadIdx.x;
    if (i >= M) return;
    int off = g_scanex[i] + g_bsum[i >> 10];
    g_rowoff[i] = off;
    g_cursor[i] = off;
}

// ---------------- 5: CSR fill (src ids only) ----------------
__global__ void edge_fill_kernel(const int* __restrict__ ei, int E, int M) {
    int i = blockIdx.x * blockDim.x + threadIdx.x;
    int total = E + M;
    if (i >= total) return;
    int s, d;
    if (i < E) { s = ei[i]; d = ei[E + i]; }
    else       { s = d = i - E; }
    int pos = atomicAdd(&g_cursor[d], 1);
    g_csrc[pos] = s;
}

// ---------------- 6: gather-aggregate (warp per node; ee recomputed) + pool ----------------
__global__ void aggregate_kernel(const int* __restrict__ batch,
                                 const float* __restrict__ bias, int M) {
    int w = blockIdx.x * (blockDim.x >> 5) + (threadIdx.x >> 5);
    if (w >= M) return;
    int lane = threadIdx.x & 31;
    int start = g_rowoff[w];
    int end   = start + g_count[w];
    int hsel  = lane >> 3;                      // head for this thread's 8 channels

    float4 ad4 = ((const float4*)g_adst)[w];
    float adh = (hsel == 0) ? ad4.x : (hsel == 1) ? ad4.y : (hsel == 2) ? ad4.z : ad4.w;

    float acc[8];
#pragma unroll
    for (int k = 0; k < 8; k++) acc[k] = 0.0f;
    float wsum = 0.0f;

    int src = 0;
    if (start < end) src = g_csrc[start];
    for (int j = start; j < end; j++) {
        int nsrc = src;
        if (j + 1 < end) nsrc = g_csrc[j + 1];
        float4 as4 = ((const float4*)g_asrc)[src];
        uint4 hv = *(const uint4*)&g_hh[(long long)src * HC + lane * 8];
        float ash = (hsel == 0) ? as4.x : (hsel == 1) ? as4.y : (hsel == 2) ? as4.z : as4.w;
        float e = ash + adh;
        e = e > 0.f ? e : 0.2f * e;
        float ee = __expf(e);
        wsum += ee;
        float2 p0 = __half22float2(*(const __half2*)&hv.x);
        float2 p1 = __half22float2(*(const __half2*)&hv.y);
        float2 p2 = __half22float2(*(const __half2*)&hv.z);
        float2 p3 = __half22float2(*(const __half2*)&hv.w);
        acc[0] += p0.x * ee; acc[1] += p0.y * ee;
        acc[2] += p1.x * ee; acc[3] += p1.y * ee;
        acc[4] += p2.x * ee; acc[5] += p2.y * ee;
        acc[6] += p3.x * ee; acc[7] += p3.y * ee;
        src = nsrc;
    }

    float inv = 1.0f / wsum;
    int b = batch[w];
    float* pp = &g_pool[b * HC + lane * 8];
#pragma unroll
    for (int k = 0; k < 8; k++) {
        float v = acc[k] * inv + bias[lane * 8 + k];
        v = v > 0.f ? v : 0.01f * v;
        atomicAdd(&pp[k], v);
    }
    if (lane == 0) atomicAdd(&g_cnt[b], 1.0f);
}

// ---------------- 7: out = meanpool @ fc1_w + fc1_b (norm fused into load) ----------------
#define FBM 32
#define FBN 64
#define SPP 260
__global__ __launch_bounds__(256)
void fc_kernel(const float* __restrict__ fc1_w,
               const float* __restrict__ fc1_b,
               float* __restrict__ out) {
    __shared__ float sp[FBM * SPP];
    __shared__ float sw[32][FBN];
    __shared__ float sinv[FBM];
    const int g0  = blockIdx.y * FBM;
    const int n0  = blockIdx.x * FBN;
    const int tid = threadIdx.x;

    if (tid < FBM) sinv[tid] = 1.0f / fmaxf(g_cnt[g0 + tid], 1.0f);
    __syncthreads();

#pragma unroll
    for (int it = 0; it < 8; it++) {
        int i = tid + it * 256;
        int r = i >> 6;
        int c = (i & 63) * 4;
        float4 v = *(const float4*)&g_pool[(g0 + r) * HC + c];
        float inv = sinv[r];
        *(float4*)&sp[r * SPP + c] = make_float4(v.x * inv, v.y * inv, v.z * inv, v.w * inv);
    }

    const int row = tid >> 3;
    const int cg  = (tid & 7) * 8;
    float acc[8];
#pragma unroll
    for (int j = 0; j < 8; j++) acc[j] = 0.0f;

    for (int k0 = 0; k0 < HC; k0 += 32) {
        __syncthreads();
#pragma unroll
        for (int it = 0; it < 2; it++) {
            int i = tid + it * 256;
            int r = i >> 4;
            int c = (i & 15) * 4;
            *(float4*)&sw[r][c] = *(const float4*)&fc1_w[(k0 + r) * FOUT + n0 + c];
        }
        __syncthreads();
#pragma unroll
        for (int kk = 0; kk < 32; kk++) {
            float p = sp[row * SPP + k0 + kk];
            float4 w0 = *(const float4*)&sw[kk][cg];
            float4 w1 = *(const float4*)&sw[kk][cg + 4];
            acc[0] += p * w0.x; acc[1] += p * w0.y;
            acc[2] += p * w0.z; acc[3] += p * w0.w;
            acc[4] += p * w1.x; acc[5] += p * w1.y;
            acc[6] += p * w1.z; acc[7] += p * w1.w;
        }
    }
#pragma unroll
    for (int j = 0; j < 8; j++) acc[j] += fc1_b[n0 + cg + j];
    *(float4*)&out[(g0 + row) * FOUT + n0 + cg]     = make_float4(acc[0], acc[1], acc[2], acc[3]);
    *(float4*)&out[(g0 + row) * FOUT + n0 + cg + 4] = make_float4(acc[4], acc[5], acc[6], acc[7]);
}

// ---------------- launch ----------------
extern "C" void kernel_launch(void* const* d_in, const int* in_sizes, int n_in,
                              void* d_out, int out_size) {
    const float* x     = (const float*)d_in[0];
    const int*   ei    = (const int*)d_in[1];
    const int*   batch = (const int*)d_in[2];
    const float* lin_w = (const float*)d_in[3];
    const float* att_s = (const float*)d_in[4];
    const float* att_d = (const float*)d_in[5];
    const float* bias  = (const float*)d_in[6];
    const float* fc1_w = (const float*)d_in[7];
    const float* fc1_b = (const float*)d_in[8];
    float* out = (float*)d_out;

    int M = in_sizes[2];       // nodes
    int E = in_sizes[1] / 2;   // edges
    int total = E + M;

    int initN = M > GRAPHS * HC ? M : GRAPHS * HC;
    init_kernel<<<(initN + 255) / 256, 256>>>(M);                      // 0

    int convN = M * (KPAD / 4);
    if (convN < KPAD * (HC / 4)) convN = KPAD * (HC / 4);
    convert_kernel<<<(convN + 255) / 256, 256>>>(x, lin_w, M);         // 1

    edge_count_kernel<<<(E + 255) / 256, 256>>>(ei, E);                // 2

    dim3 ggrid(2, (M + BM - 1) / BM);
    gemm_h_kernel<<<ggrid, 256>>>(att_s, att_d, M);                    // 3 <- ncu slot

    int nb = (M + 1023) / 1024;
    scan1_kernel<<<nb, 1024>>>(M);                                     // 4
    scan2_kernel<<<1, 64>>>(nb);                                       // 5
    scan3_kernel<<<(M + 255) / 256, 256>>>(M);                         // 6

    edge_fill_kernel<<<(total + 255) / 256, 256>>>(ei, E, M);          // 7

    aggregate_kernel<<<(M * 32 + 255) / 256, 256>>>(batch, bias, M);   // 8

    dim3 fgrid(FOUT / FBN, GRAPHS / FBM);
    fc_kernel<<<fgrid, 256>>>(fc1_w, fc1_b, out);                      // 9
}